// round 3
// baseline (speedup 1.0000x reference)
#include <cuda_runtime.h>
#include <math.h>

// ---------------------------------------------------------------------------
// CriticLSTM: obs(B,S,3,33) + act(B,S,3,4) -> concat D=111 -> LSTM(H=128)
//             -> MLP 128->256->128->1.  Outputs: q (B*S), hT (B*H), cT (B*H).
// B=1024, S=512. All fp32.
//
// Phases (all on default stream, graph-capturable, allocation-free):
//   prep : transpose weights into __device__ scratch (coalesced GEMM loads)
//   gx   : gx[tok][512] = x @ W_ih^T + (b_ih+b_hh)        (parallel GEMM)
//   lstm : 128 CTAs x 8 batch rows, 512 sequential steps  (batch-parallel)
//   mlp1 : y1 = relu(h @ W1^T + b1)                        (parallel GEMM)
//   mlp2 : q  = relu(y1 @ W2^T + b2) @ W3^T + b3           (parallel GEMM)
// ---------------------------------------------------------------------------

#define BB    1024
#define SS    512
#define DIN   111
#define DPAD  112
#define HH    128
#define G4    512          // 4*H
#define NTOK  (BB * SS)    // 524288

// Scratch (device globals: the sanctioned allocation-free scratch path)
__device__ float d_gx  [(size_t)NTOK * G4];   // 1 GiB
__device__ float d_hseq[(size_t)NTOK * HH];   // 256 MiB
__device__ float d_y1  [(size_t)NTOK * 256];  // 512 MiB
__device__ float d_WTih[DPAD * G4];           // W_ih^T padded to 112 rows
__device__ float d_WThh[HH * G4];             // W_hh^T
__device__ float d_WT1 [HH * 256];            // W1^T
__device__ float d_WT2 [256 * HH];            // W2^T
__device__ float d_bihh[G4];                  // b_ih + b_hh

// ---------------------------------------------------------------------------
// prep: build transposed weight copies + combined bias
// ---------------------------------------------------------------------------
#define PREP_N0 (DPAD * G4)            // 57344
#define PREP_N1 (HH * G4)              // 65536
#define PREP_N2 (HH * 256)             // 32768
#define PREP_N3 (256 * HH)             // 32768
#define PREP_N4 (G4)                   // 512
#define PREP_TOTAL (PREP_N0 + PREP_N1 + PREP_N2 + PREP_N3 + PREP_N4)

__global__ void prep_kernel(const float* __restrict__ W_ih,
                            const float* __restrict__ W_hh,
                            const float* __restrict__ b_ih,
                            const float* __restrict__ b_hh,
                            const float* __restrict__ W1,
                            const float* __restrict__ W2) {
    int idx = blockIdx.x * blockDim.x + threadIdx.x;
    if (idx < PREP_N0) {
        int k = idx >> 9, j = idx & 511;
        d_WTih[idx] = (k < DIN) ? W_ih[j * DIN + k] : 0.0f;
        return;
    }
    idx -= PREP_N0;
    if (idx < PREP_N1) {
        int k = idx >> 9, j = idx & 511;
        d_WThh[k * G4 + j] = W_hh[j * HH + k];
        return;
    }
    idx -= PREP_N1;
    if (idx < PREP_N2) {
        int k = idx >> 8, j = idx & 255;
        d_WT1[k * 256 + j] = W1[j * HH + k];
        return;
    }
    idx -= PREP_N2;
    if (idx < PREP_N3) {
        int k = idx >> 7, j = idx & 127;
        d_WT2[k * HH + j] = W2[j * 256 + k];
        return;
    }
    idx -= PREP_N3;
    if (idx < PREP_N4) {
        d_bihh[idx] = b_ih[idx] + b_hh[idx];
    }
}

// ---------------------------------------------------------------------------
// gx kernel: 1024 CTAs x 512 threads, 512 tokens/CTA, tile T=8
// thread j owns gate-output j; weights coalesced from global (L1-resident)
// ---------------------------------------------------------------------------
__global__ __launch_bounds__(512) void gx_kernel(const float* __restrict__ obs,
                                                 const float* __restrict__ act) {
    __shared__ float sx[8][DPAD];
    const int j = threadIdx.x;
    const float bj = d_bihh[j];
    const int tokbase = blockIdx.x * 512;

    for (int tile = 0; tile < 64; ++tile) {
        const int tok0 = tokbase + tile * 8;
        __syncthreads();
        for (int idx = j; idx < 8 * 99; idx += 512) {
            int t = idx / 99, k = idx - t * 99;
            sx[t][k] = obs[(size_t)(tok0 + t) * 99 + k];
        }
        if (j < 96) {
            int t = j / 12, k = j - t * 12;
            sx[t][99 + k] = act[(size_t)(tok0 + t) * 12 + k];
        }
        if (j < 8) sx[j][111] = 0.0f;
        __syncthreads();

        float acc[8];
        #pragma unroll
        for (int r = 0; r < 8; ++r) acc[r] = bj;

        #pragma unroll 2
        for (int kc = 0; kc < DPAD; kc += 4) {
            const float w0 = d_WTih[(kc + 0) * G4 + j];
            const float w1 = d_WTih[(kc + 1) * G4 + j];
            const float w2 = d_WTih[(kc + 2) * G4 + j];
            const float w3 = d_WTih[(kc + 3) * G4 + j];
            #pragma unroll
            for (int r = 0; r < 8; ++r) {
                const float4 xv = *(const float4*)&sx[r][kc];
                acc[r] = fmaf(xv.x, w0, acc[r]);
                acc[r] = fmaf(xv.y, w1, acc[r]);
                acc[r] = fmaf(xv.z, w2, acc[r]);
                acc[r] = fmaf(xv.w, w3, acc[r]);
            }
        }
        #pragma unroll
        for (int r = 0; r < 8; ++r)
            d_gx[(size_t)(tok0 + r) * G4 + j] = acc[r];
    }
}

// ---------------------------------------------------------------------------
// lstm kernel: 128 CTAs x 512 threads; CTA owns 8 batch rows for all 512 steps
// ---------------------------------------------------------------------------
__device__ __forceinline__ float sigmoidf_(float x) {
    return 1.0f / (1.0f + expf(-x));
}

__global__ __launch_bounds__(512) void lstm_kernel(float* __restrict__ d_out) {
    __shared__ float sh_h[8][HH];   // 4 KB
    __shared__ float sh_g[8][G4];   // 16 KB
    const int j  = threadIdx.x;
    const int b0 = blockIdx.x * 8;
    const int u  = j & 127;        // hidden unit
    const int ra = j >> 7;         // rows handled in gate phase: ra and ra+4
    const int rb = ra + 4;

    for (int idx = j; idx < 8 * HH; idx += 512) ((float*)sh_h)[idx] = 0.0f;
    float ca = 0.0f, cb = 0.0f;
    __syncthreads();

    for (int t = 0; t < SS; ++t) {
        // prefetch gx for this step (consumed only after the GEMM -> latency hidden)
        float gxv[8];
        #pragma unroll
        for (int r = 0; r < 8; ++r)
            gxv[r] = d_gx[((size_t)(b0 + r) * SS + t) * G4 + j];

        float acc[8];
        #pragma unroll
        for (int r = 0; r < 8; ++r) acc[r] = 0.0f;

        #pragma unroll 2
        for (int kc = 0; kc < HH; kc += 4) {
            const float w0 = d_WThh[(kc + 0) * G4 + j];
            const float w1 = d_WThh[(kc + 1) * G4 + j];
            const float w2 = d_WThh[(kc + 2) * G4 + j];
            const float w3 = d_WThh[(kc + 3) * G4 + j];
            #pragma unroll
            for (int r = 0; r < 8; ++r) {
                const float4 hv = *(const float4*)&sh_h[r][kc];
                acc[r] = fmaf(hv.x, w0, acc[r]);
                acc[r] = fmaf(hv.y, w1, acc[r]);
                acc[r] = fmaf(hv.z, w2, acc[r]);
                acc[r] = fmaf(hv.w, w3, acc[r]);
            }
        }
        #pragma unroll
        for (int r = 0; r < 8; ++r) sh_g[r][j] = acc[r] + gxv[r];
        __syncthreads();

        // gate phase: each thread updates (ra,u) and (rb,u)
        {
            float i1 = sigmoidf_(sh_g[ra][u]);
            float f1 = sigmoidf_(sh_g[ra][128 + u]);
            float g1 = tanhf   (sh_g[ra][256 + u]);
            float o1 = sigmoidf_(sh_g[ra][384 + u]);
            float i2 = sigmoidf_(sh_g[rb][u]);
            float f2 = sigmoidf_(sh_g[rb][128 + u]);
            float g2 = tanhf   (sh_g[rb][256 + u]);
            float o2 = sigmoidf_(sh_g[rb][384 + u]);
            ca = f1 * ca + i1 * g1;
            cb = f2 * cb + i2 * g2;
            const float h1 = o1 * tanhf(ca);
            const float h2 = o2 * tanhf(cb);
            sh_h[ra][u] = h1;
            sh_h[rb][u] = h2;
            d_hseq[((size_t)(b0 + ra) * SS + t) * HH + u] = h1;
            d_hseq[((size_t)(b0 + rb) * SS + t) * HH + u] = h2;
        }
        __syncthreads();
    }

    // final hT / cT:  d_out = [ q (NTOK) | hT (B*H) | cT (B*H) ]
    const size_t HOFF = (size_t)NTOK;
    const size_t COFF = (size_t)NTOK + (size_t)BB * HH;
    d_out[HOFF + (size_t)(b0 + ra) * HH + u] = sh_h[ra][u];
    d_out[HOFF + (size_t)(b0 + rb) * HH + u] = sh_h[rb][u];
    d_out[COFF + (size_t)(b0 + ra) * HH + u] = ca;
    d_out[COFF + (size_t)(b0 + rb) * HH + u] = cb;
}

// ---------------------------------------------------------------------------
// mlp1: y1 = relu(h @ W1^T + b1).  2048 CTAs x 256 thr, 256 tok/CTA, tile 16
// ---------------------------------------------------------------------------
__global__ __launch_bounds__(256) void mlp1_kernel(const float* __restrict__ b1) {
    __shared__ float shx[16][HH];  // 8 KB
    const int j = threadIdx.x;     // output neuron 0..255
    const float bj = b1[j];
    const int tokbase = blockIdx.x * 256;

    for (int tile = 0; tile < 16; ++tile) {
        const int tok0 = tokbase + tile * 16;
        __syncthreads();
        for (int idx = j; idx < 16 * HH; idx += 256)
            ((float*)shx)[idx] = d_hseq[(size_t)tok0 * HH + idx];
        __syncthreads();

        float acc[16];
        #pragma unroll
        for (int r = 0; r < 16; ++r) acc[r] = bj;

        #pragma unroll 2
        for (int kc = 0; kc < HH; kc += 4) {
            const float w0 = d_WT1[(kc + 0) * 256 + j];
            const float w1 = d_WT1[(kc + 1) * 256 + j];
            const float w2 = d_WT1[(kc + 2) * 256 + j];
            const float w3 = d_WT1[(kc + 3) * 256 + j];
            #pragma unroll
            for (int r = 0; r < 16; ++r) {
                const float4 xv = *(const float4*)&shx[r][kc];
                acc[r] = fmaf(xv.x, w0, acc[r]);
                acc[r] = fmaf(xv.y, w1, acc[r]);
                acc[r] = fmaf(xv.z, w2, acc[r]);
                acc[r] = fmaf(xv.w, w3, acc[r]);
            }
        }
        #pragma unroll
        for (int r = 0; r < 16; ++r)
            d_y1[(size_t)(tok0 + r) * 256 + j] = fmaxf(acc[r], 0.0f);
    }
}

// ---------------------------------------------------------------------------
// mlp2: y2 = relu(y1 @ W2^T + b2); q = y2 . w3 + b3
// 2048 CTAs x 256 thr, 256 tok/CTA, tile 16.
// threads split: (half = j>>7) handles 8 tokens, output unit u = j&127.
// ---------------------------------------------------------------------------
__global__ __launch_bounds__(256) void mlp2_kernel(const float* __restrict__ b2,
                                                   const float* __restrict__ W3,
                                                   const float* __restrict__ b3,
                                                   float* __restrict__ d_out) {
    __shared__ float shy1[16][256];  // 16 KB
    __shared__ float shy2[16][HH];   //  8 KB
    const int j    = threadIdx.x;
    const int u    = j & 127;
    const int half = j >> 7;
    const int lane = j & 31;
    const int wrp  = j >> 5;         // 0..7
    const float bu  = b2[u];
    const float w3a = W3[lane], w3b = W3[32 + lane];
    const float w3c = W3[64 + lane], w3d = W3[96 + lane];
    const float b3v = b3[0];
    const int tokbase = blockIdx.x * 256;

    for (int tile = 0; tile < 16; ++tile) {
        const int tok0 = tokbase + tile * 16;
        __syncthreads();
        for (int idx = j; idx < 16 * 256; idx += 256)
            ((float*)shy1)[idx] = d_y1[(size_t)tok0 * 256 + idx];
        __syncthreads();

        float acc[8];
        #pragma unroll
        for (int r = 0; r < 8; ++r) acc[r] = bu;

        #pragma unroll 2
        for (int kc = 0; kc < 256; kc += 4) {
            const float w0 = d_WT2[(kc + 0) * HH + u];
            const float w1 = d_WT2[(kc + 1) * HH + u];
            const float w2 = d_WT2[(kc + 2) * HH + u];
            const float w3w = d_WT2[(kc + 3) * HH + u];
            #pragma unroll
            for (int r = 0; r < 8; ++r) {
                const float4 yv = *(const float4*)&shy1[half * 8 + r][kc];
                acc[r] = fmaf(yv.x, w0, acc[r]);
                acc[r] = fmaf(yv.y, w1, acc[r]);
                acc[r] = fmaf(yv.z, w2, acc[r]);
                acc[r] = fmaf(yv.w, w3w, acc[r]);
            }
        }
        #pragma unroll
        for (int r = 0; r < 8; ++r)
            shy2[half * 8 + r][u] = fmaxf(acc[r], 0.0f);
        __syncthreads();

        // q: warp wrp reduces tokens 2*wrp and 2*wrp+1
        #pragma unroll
        for (int tt = 0; tt < 2; ++tt) {
            const int t = wrp * 2 + tt;
            float s = shy2[t][lane]      * w3a
                    + shy2[t][32 + lane] * w3b
                    + shy2[t][64 + lane] * w3c
                    + shy2[t][96 + lane] * w3d;
            #pragma unroll
            for (int off = 16; off > 0; off >>= 1)
                s += __shfl_down_sync(0xffffffffu, s, off);
            if (lane == 0) d_out[tok0 + t] = s + b3v;
        }
    }
}

// ---------------------------------------------------------------------------
// launch
// ---------------------------------------------------------------------------
extern "C" void kernel_launch(void* const* d_in, const int* in_sizes, int n_in,
                              void* d_out, int out_size) {
    const float* obs  = (const float*)d_in[0];
    const float* act  = (const float*)d_in[1];
    const float* W_ih = (const float*)d_in[2];
    const float* W_hh = (const float*)d_in[3];
    const float* b_ih = (const float*)d_in[4];
    const float* b_hh = (const float*)d_in[5];
    const float* W1   = (const float*)d_in[6];
    const float* b1   = (const float*)d_in[7];
    const float* W2   = (const float*)d_in[8];
    const float* b2   = (const float*)d_in[9];
    const float* W3   = (const float*)d_in[10];
    const float* b3   = (const float*)d_in[11];
    float* out = (float*)d_out;

    prep_kernel<<<(PREP_TOTAL + 255) / 256, 256>>>(W_ih, W_hh, b_ih, b_hh, W1, W2);
    gx_kernel  <<<1024, 512>>>(obs, act);
    lstm_kernel<<<128, 512>>>(out);
    mlp1_kernel<<<2048, 256>>>(b1);
    mlp2_kernel<<<2048, 256>>>(b2, W3, b3, out);
}

// round 5
// speedup vs baseline: 1.1309x; 1.1309x over previous
#include <cuda_runtime.h>
#include <math.h>

// ---------------------------------------------------------------------------
// CriticLSTM: obs(B,S,3,33)+act(B,S,3,4) -> concat D=111 -> LSTM(H=128)
//             -> MLP 128->256->128->1. Outputs: q (B*S), hT (B*H), cT (B*H).
// B=1024, S=512, fp32.
//
// Packed fma.rn.f32x2 (SASS FFMA2, 2 FMA per fma-pipe issue) with
// row-pair-packed transposed smem activations; fused MLP (no d_y1 trip);
// fast __expf-based gates on the serial LSTM path.
// (Resubmission: Round-3 source never executed — container infra failure.)
// ---------------------------------------------------------------------------

#define BB    1024
#define SS    512
#define DIN   111
#define DPAD  112
#define HH    128
#define G4    512
#define NTOK  (BB * SS)

typedef unsigned long long ull;

__device__ __forceinline__ ull ffma2(ull a, ull b, ull c) {
    ull d;
    asm("fma.rn.f32x2 %0, %1, %2, %3;" : "=l"(d) : "l"(a), "l"(b), "l"(c));
    return d;
}
__device__ __forceinline__ ull packdup(float x) {
    ull d;
    asm("mov.b64 %0, {%1, %2};" : "=l"(d) : "f"(x), "f"(x));
    return d;
}
__device__ __forceinline__ float2 unpack2(ull v) {
    float2 r;
    asm("mov.b64 {%0, %1}, %2;" : "=f"(r.x), "=f"(r.y) : "l"(v));
    return r;
}
__device__ __forceinline__ float fast_sigmoid(float x) {
    return __fdividef(1.0f, 1.0f + __expf(-x));
}
__device__ __forceinline__ float fast_tanh(float x) {
    return __fdividef(2.0f, 1.0f + __expf(-2.0f * x)) - 1.0f;
}

// Scratch (device globals: sanctioned allocation-free scratch)
__device__ float d_gx  [(size_t)NTOK * G4];   // 1 GiB
__device__ float d_hseq[(size_t)NTOK * HH];   // 256 MiB
__device__ float d_WTih[DPAD * G4];           // W_ih^T (padded 112 rows)
__device__ float d_WThh[HH * G4];             // W_hh^T
__device__ float d_WT1 [HH * 256];            // W1^T
__device__ float d_WT2 [256 * HH];            // W2^T
__device__ float d_bihh[G4];                  // b_ih + b_hh

// ---------------------------------------------------------------------------
// prep: transposed weight copies + combined bias
// ---------------------------------------------------------------------------
#define PREP_N0 (DPAD * G4)
#define PREP_N1 (HH * G4)
#define PREP_N2 (HH * 256)
#define PREP_N3 (256 * HH)
#define PREP_N4 (G4)
#define PREP_TOTAL (PREP_N0 + PREP_N1 + PREP_N2 + PREP_N3 + PREP_N4)

__global__ void prep_kernel(const float* __restrict__ W_ih,
                            const float* __restrict__ W_hh,
                            const float* __restrict__ b_ih,
                            const float* __restrict__ b_hh,
                            const float* __restrict__ W1,
                            const float* __restrict__ W2) {
    int idx = blockIdx.x * blockDim.x + threadIdx.x;
    if (idx < PREP_N0) {
        int k = idx >> 9, j = idx & 511;
        d_WTih[idx] = (k < DIN) ? W_ih[j * DIN + k] : 0.0f;
        return;
    }
    idx -= PREP_N0;
    if (idx < PREP_N1) {
        int k = idx >> 9, j = idx & 511;
        d_WThh[k * G4 + j] = W_hh[j * HH + k];
        return;
    }
    idx -= PREP_N1;
    if (idx < PREP_N2) {
        int k = idx >> 8, j = idx & 255;
        d_WT1[k * 256 + j] = W1[j * HH + k];
        return;
    }
    idx -= PREP_N2;
    if (idx < PREP_N3) {
        int k = idx >> 7, j = idx & 127;
        d_WT2[k * HH + j] = W2[j * 256 + k];
        return;
    }
    idx -= PREP_N3;
    if (idx < PREP_N4) d_bihh[idx] = b_ih[idx] + b_hh[idx];
}

// ---------------------------------------------------------------------------
// gx: gx[tok][512] = x @ W_ih^T + (b_ih+b_hh)
// 1024 CTAs x 512 thr; 512 tok/CTA, 32 tiles of 16 tokens (8 packed pairs).
// smem activations transposed [k][t], row stride 20 floats (16B aligned).
// ---------------------------------------------------------------------------
#define GX_STR 20
__global__ __launch_bounds__(512) void gx_kernel(const float* __restrict__ obs,
                                                 const float* __restrict__ act) {
    __shared__ __align__(16) float sxT[DPAD * GX_STR];
    const int j = threadIdx.x;
    const float bj = d_bihh[j];
    const int tokbase = blockIdx.x * 512;

    for (int tile = 0; tile < 32; ++tile) {
        const int tok0 = tokbase + tile * 16;
        __syncthreads();
        for (int idx = j; idx < 16 * 99; idx += 512) {
            int t = idx / 99, k = idx - t * 99;
            sxT[k * GX_STR + t] = obs[(size_t)(tok0 + t) * 99 + k];
        }
        if (j < 16 * 12) {
            int t = j / 12, k = j - t * 12;
            sxT[(99 + k) * GX_STR + t] = act[(size_t)(tok0 + t) * 12 + k];
        }
        if (j < 16) sxT[111 * GX_STR + j] = 0.0f;
        __syncthreads();

        ull acc[8];
        #pragma unroll
        for (int p = 0; p < 8; ++p) acc[p] = packdup(bj);

        #pragma unroll 2
        for (int kc = 0; kc < DPAD; kc += 4) {
            ull W[4];
            #pragma unroll
            for (int q = 0; q < 4; ++q)
                W[q] = packdup(d_WTih[(kc + q) * G4 + j]);
            #pragma unroll
            for (int q = 0; q < 4; ++q) {
                const ulonglong2* row =
                    (const ulonglong2*)&sxT[(kc + q) * GX_STR];
                ulonglong2 v0 = row[0], v1 = row[1], v2 = row[2], v3 = row[3];
                acc[0] = ffma2(v0.x, W[q], acc[0]);
                acc[1] = ffma2(v0.y, W[q], acc[1]);
                acc[2] = ffma2(v1.x, W[q], acc[2]);
                acc[3] = ffma2(v1.y, W[q], acc[3]);
                acc[4] = ffma2(v2.x, W[q], acc[4]);
                acc[5] = ffma2(v2.y, W[q], acc[5]);
                acc[6] = ffma2(v3.x, W[q], acc[6]);
                acc[7] = ffma2(v3.y, W[q], acc[7]);
            }
        }
        #pragma unroll
        for (int p = 0; p < 8; ++p) {
            float2 r = unpack2(acc[p]);
            d_gx[(size_t)(tok0 + 2 * p)     * G4 + j] = r.x;
            d_gx[(size_t)(tok0 + 2 * p + 1) * G4 + j] = r.y;
        }
    }
}

// ---------------------------------------------------------------------------
// lstm: 128 CTAs x 512 thr; CTA owns 8 batch rows (4 packed pairs), 512 steps.
// h kept transposed in smem [k][row], stride 12 floats.
// ---------------------------------------------------------------------------
#define H_STR 12
__global__ __launch_bounds__(512) void lstm_kernel(float* __restrict__ d_out) {
    __shared__ __align__(16) float sh_hT[HH * H_STR];  // 6 KB
    __shared__ float sh_g[8 * G4];                      // 16 KB
    const int j  = threadIdx.x;
    const int b0 = blockIdx.x * 8;
    const int u  = j & 127;
    const int ra = j >> 7;          // gate-phase rows ra, ra+4
    const int rb = ra + 4;

    for (int idx = j; idx < HH * H_STR; idx += 512) sh_hT[idx] = 0.0f;
    float ca = 0.0f, cb = 0.0f;
    __syncthreads();

    for (int t = 0; t < SS; ++t) {
        float gxv[8];
        #pragma unroll
        for (int r = 0; r < 8; ++r)
            gxv[r] = d_gx[((size_t)(b0 + r) * SS + t) * G4 + j];

        ull acc[4] = {0ull, 0ull, 0ull, 0ull};

        #pragma unroll 2
        for (int kc = 0; kc < HH; kc += 4) {
            ull W[4];
            #pragma unroll
            for (int q = 0; q < 4; ++q)
                W[q] = packdup(d_WThh[(kc + q) * G4 + j]);
            #pragma unroll
            for (int q = 0; q < 4; ++q) {
                const ulonglong2* row =
                    (const ulonglong2*)&sh_hT[(kc + q) * H_STR];
                ulonglong2 v0 = row[0], v1 = row[1];
                acc[0] = ffma2(v0.x, W[q], acc[0]);
                acc[1] = ffma2(v0.y, W[q], acc[1]);
                acc[2] = ffma2(v1.x, W[q], acc[2]);
                acc[3] = ffma2(v1.y, W[q], acc[3]);
            }
        }
        #pragma unroll
        for (int p = 0; p < 4; ++p) {
            float2 r = unpack2(acc[p]);
            sh_g[(2 * p)     * G4 + j] = r.x + gxv[2 * p];
            sh_g[(2 * p + 1) * G4 + j] = r.y + gxv[2 * p + 1];
        }
        __syncthreads();

        {
            float i1 = fast_sigmoid(sh_g[ra * G4 + u]);
            float f1 = fast_sigmoid(sh_g[ra * G4 + 128 + u]);
            float g1 = fast_tanh   (sh_g[ra * G4 + 256 + u]);
            float o1 = fast_sigmoid(sh_g[ra * G4 + 384 + u]);
            float i2 = fast_sigmoid(sh_g[rb * G4 + u]);
            float f2 = fast_sigmoid(sh_g[rb * G4 + 128 + u]);
            float g2 = fast_tanh   (sh_g[rb * G4 + 256 + u]);
            float o2 = fast_sigmoid(sh_g[rb * G4 + 384 + u]);
            ca = f1 * ca + i1 * g1;
            cb = f2 * cb + i2 * g2;
            const float h1 = o1 * fast_tanh(ca);
            const float h2 = o2 * fast_tanh(cb);
            sh_hT[u * H_STR + ra] = h1;
            sh_hT[u * H_STR + rb] = h2;
            d_hseq[((size_t)(b0 + ra) * SS + t) * HH + u] = h1;
            d_hseq[((size_t)(b0 + rb) * SS + t) * HH + u] = h2;
        }
        __syncthreads();
    }

    const size_t HOFF = (size_t)NTOK;
    const size_t COFF = (size_t)NTOK + (size_t)BB * HH;
    d_out[HOFF + (size_t)(b0 + ra) * HH + u] = sh_hT[u * H_STR + ra];
    d_out[HOFF + (size_t)(b0 + rb) * HH + u] = sh_hT[u * H_STR + rb];
    d_out[COFF + (size_t)(b0 + ra) * HH + u] = ca;
    d_out[COFF + (size_t)(b0 + rb) * HH + u] = cb;
}

// ---------------------------------------------------------------------------
// fused MLP: y1 = relu(h@W1^T+b1); y2 = relu(y1@W2^T+b2); q = y2.w3 + b3
// 2048 CTAs x 256 thr; 256 tok/CTA, 16 tiles of 16 tokens.
// ---------------------------------------------------------------------------
#define X_STR 20
__global__ __launch_bounds__(256) void mlp_kernel(const float* __restrict__ b1,
                                                  const float* __restrict__ b2,
                                                  const float* __restrict__ W3,
                                                  const float* __restrict__ b3,
                                                  float* __restrict__ d_out) {
    __shared__ __align__(16) float shxT [HH  * X_STR];  // 10 KB  [k][t]
    __shared__ __align__(16) float shy1T[256 * X_STR];  // 20 KB  [neuron][t]
    __shared__ __align__(16) float shy2 [16 * HH];      //  8 KB  [t][u]
    const int j    = threadIdx.x;       // 0..255
    const int u    = j & 127;
    const int half = j >> 7;            // token half for stage C
    const int lane = j & 31;
    const int wrp  = j >> 5;            // 0..7
    const float b1j = b1[j];
    const float b2u = b2[u];
    const float w3a = W3[lane],      w3b = W3[32 + lane];
    const float w3c = W3[64 + lane], w3d = W3[96 + lane];
    const float b3v = b3[0];
    const int tokbase = blockIdx.x * 256;

    for (int tile = 0; tile < 16; ++tile) {
        const int tok0 = tokbase + tile * 16;
        __syncthreads();
        // stage A: load h tile transposed
        #pragma unroll
        for (int it = 0; it < 8; ++it) {
            int idx = j + it * 256;                // 0..2047
            int t = idx >> 7, k = idx & 127;
            shxT[k * X_STR + t] = d_hseq[(size_t)tok0 * HH + idx];
        }
        __syncthreads();

        // stage B: y1 neuron j for 16 tokens (8 pairs)
        {
            ull acc[8];
            #pragma unroll
            for (int p = 0; p < 8; ++p) acc[p] = packdup(b1j);
            #pragma unroll 2
            for (int kc = 0; kc < HH; kc += 4) {
                ull W[4];
                #pragma unroll
                for (int q = 0; q < 4; ++q)
                    W[q] = packdup(d_WT1[(kc + q) * 256 + j]);
                #pragma unroll
                for (int q = 0; q < 4; ++q) {
                    const ulonglong2* row =
                        (const ulonglong2*)&shxT[(kc + q) * X_STR];
                    ulonglong2 v0 = row[0], v1 = row[1], v2 = row[2], v3 = row[3];
                    acc[0] = ffma2(v0.x, W[q], acc[0]);
                    acc[1] = ffma2(v0.y, W[q], acc[1]);
                    acc[2] = ffma2(v1.x, W[q], acc[2]);
                    acc[3] = ffma2(v1.y, W[q], acc[3]);
                    acc[4] = ffma2(v2.x, W[q], acc[4]);
                    acc[5] = ffma2(v2.y, W[q], acc[5]);
                    acc[6] = ffma2(v3.x, W[q], acc[6]);
                    acc[7] = ffma2(v3.y, W[q], acc[7]);
                }
            }
            #pragma unroll
            for (int p = 0; p < 8; ++p) {
                float2 r = unpack2(acc[p]);
                shy1T[j * X_STR + 2 * p]     = fmaxf(r.x, 0.0f);
                shy1T[j * X_STR + 2 * p + 1] = fmaxf(r.y, 0.0f);
            }
        }
        __syncthreads();

        // stage C: y2 unit u for 8 tokens (half) (4 pairs)
        {
            ull acc[4];
            #pragma unroll
            for (int p = 0; p < 4; ++p) acc[p] = packdup(b2u);
            #pragma unroll 2
            for (int kc = 0; kc < 256; kc += 4) {
                ull W[4];
                #pragma unroll
                for (int q = 0; q < 4; ++q)
                    W[q] = packdup(d_WT2[(kc + q) * HH + u]);
                #pragma unroll
                for (int q = 0; q < 4; ++q) {
                    const ulonglong2* row = (const ulonglong2*)
                        &shy1T[(kc + q) * X_STR + half * 8];
                    ulonglong2 v0 = row[0], v1 = row[1];
                    acc[0] = ffma2(v0.x, W[q], acc[0]);
                    acc[1] = ffma2(v0.y, W[q], acc[1]);
                    acc[2] = ffma2(v1.x, W[q], acc[2]);
                    acc[3] = ffma2(v1.y, W[q], acc[3]);
                }
            }
            #pragma unroll
            for (int p = 0; p < 4; ++p) {
                float2 r = unpack2(acc[p]);
                int t0 = half * 8 + 2 * p;
                shy2[t0 * HH + u]       = fmaxf(r.x, 0.0f);
                shy2[(t0 + 1) * HH + u] = fmaxf(r.y, 0.0f);
            }
        }
        __syncthreads();

        // q reduction: warp wrp handles tokens 2*wrp, 2*wrp+1
        #pragma unroll
        for (int tt = 0; tt < 2; ++tt) {
            const int t = wrp * 2 + tt;
            float s = shy2[t * HH + lane]      * w3a
                    + shy2[t * HH + 32 + lane] * w3b
                    + shy2[t * HH + 64 + lane] * w3c
                    + shy2[t * HH + 96 + lane] * w3d;
            #pragma unroll
            for (int off = 16; off > 0; off >>= 1)
                s += __shfl_down_sync(0xffffffffu, s, off);
            if (lane == 0) d_out[tok0 + t] = s + b3v;
        }
    }
}

// ---------------------------------------------------------------------------
// launch
// ---------------------------------------------------------------------------
extern "C" void kernel_launch(void* const* d_in, const int* in_sizes, int n_in,
                              void* d_out, int out_size) {
    const float* obs  = (const float*)d_in[0];
    const float* act  = (const float*)d_in[1];
    const float* W_ih = (const float*)d_in[2];
    const float* W_hh = (const float*)d_in[3];
    const float* b_ih = (const float*)d_in[4];
    const float* b_hh = (const float*)d_in[5];
    const float* W1   = (const float*)d_in[6];
    const float* b1   = (const float*)d_in[7];
    const float* W2   = (const float*)d_in[8];
    const float* b2   = (const float*)d_in[9];
    const float* W3   = (const float*)d_in[10];
    const float* b3   = (const float*)d_in[11];
    float* out = (float*)d_out;

    prep_kernel<<<(PREP_TOTAL + 255) / 256, 256>>>(W_ih, W_hh, b_ih, b_hh, W1, W2);
    gx_kernel  <<<1024, 512>>>(obs, act);
    lstm_kernel<<<128, 512>>>(out);
    mlp_kernel <<<2048, 256>>>(b1, b2, W3, b3, out);
}